// round 15
// baseline (speedup 1.0000x reference)
#include <cuda_runtime.h>
#include <cuda_bf16.h>
#include <cstdint>
#include <cstddef>

#define S_    128
#define B_    64
#define V_    32000
#define E_    32
#define H_    16
#define ROWS  8192
#define VQ    8000              // cols per v-quarter
#define WCOLS 2000              // cols per warp
#define NGRP  (WCOLS / 16)      // 125 iterations, 16 cols each
#define NPART 16                // 4 v-quarters x 4 warps

// ---------------- device scratch ----------------
__device__ float g_xw[ROWS * H_];
__device__ float g_h[ROWS * H_];
__device__ float g_part[NPART * ROWS];

// ---------------- helpers ----------------
__device__ __forceinline__ uint32_t bf16x2_of(float lo, float hi) {
    uint32_t r;
    asm("cvt.rn.bf16x2.f32 %0, %1, %2;" : "=r"(r) : "f"(hi), "f"(lo));
    return r;
}
__device__ __forceinline__ void mma_bf16(float& c0, float& c1, float& c2, float& c3,
                                         const uint32_t a[4], uint32_t b0, uint32_t b1) {
    asm volatile(
        "mma.sync.aligned.m16n8k16.row.col.f32.bf16.bf16.f32 "
        "{%0,%1,%2,%3}, {%4,%5,%6,%7}, {%8,%9}, {%0,%1,%2,%3};"
        : "+f"(c0), "+f"(c1), "+f"(c2), "+f"(c3)
        : "r"(a[0]), "r"(a[1]), "r"(a[2]), "r"(a[3]), "r"(b0), "r"(b1));
}
__device__ __forceinline__ void cp8(uint32_t sa, const void* ga) {
    asm volatile("cp.async.ca.shared.global [%0], [%1], 8;" :: "r"(sa), "l"(ga));
}
__device__ __forceinline__ void cp_commit() {
    asm volatile("cp.async.commit_group;" ::: "memory");
}
__device__ __forceinline__ void cp_wait1() {
    asm volatile("cp.async.wait_group 1;" ::: "memory");
}

// ---------------- k1: xw = lookup[idx] @ Wx ----------------
__global__ void k_embed_xw(const int* __restrict__ idx,
                           const float* __restrict__ lookup,
                           const float* __restrict__ wx) {
    __shared__ float sWx[E_ * H_];
    for (int i = threadIdx.x; i < E_ * H_; i += blockDim.x) sWx[i] = wx[i];
    __syncthreads();
    int r = blockIdx.x * blockDim.x + threadIdx.x;
    int id = idx[r];
    float x[E_];
    const float4* lp = reinterpret_cast<const float4*>(lookup + (size_t)id * E_);
    #pragma unroll
    for (int i = 0; i < E_ / 4; i++) {
        float4 t = lp[i];
        x[4*i] = t.x; x[4*i+1] = t.y; x[4*i+2] = t.z; x[4*i+3] = t.w;
    }
    #pragma unroll
    for (int h = 0; h < H_; h++) {
        float a = 0.f;
        #pragma unroll
        for (int e = 0; e < E_; e++) a += x[e] * sWx[e * H_ + h];
        g_xw[r * H_ + h] = a;
    }
}

// ---------------- k2: sequential recurrence (ping-pong) ----------------
__global__ void k_rnn(const float* __restrict__ wh, const float* __restrict__ h0) {
    __shared__ float sWh[H_ * H_];
    __shared__ float sh[2][B_ * H_];
    int tid = threadIdx.x;                 // 1024 threads
    if (tid < H_ * H_) sWh[tid] = wh[tid];
    sh[0][tid] = h0[tid];
    __syncthreads();
    int b = tid >> 4, j = tid & 15;
    float pre = g_xw[tid];
    #pragma unroll 2
    for (int s = 0; s < S_; s++) {
        int p = s & 1;
        float a = pre;
        float nxt = (s < S_ - 1) ? g_xw[(s + 1) * (B_ * H_) + tid] : 0.f;
        #pragma unroll
        for (int k = 0; k < H_; k++) a += sh[p][b * H_ + k] * sWh[k * H_ + j];
        float hn = tanhf(a);
        sh[p ^ 1][tid] = hn;
        g_h[s * (B_ * H_) + tid] = hn;
        pre = nxt;
        __syncthreads();
    }
}

// ---------------- projection: mma.sync bf16, 32 rows/CTA (2 m-tiles/warp) --
// B staged via warp-private cp.async pipeline (3 stages): each lane async-
// copies the exact 4 float2 it consumes -> per-lane SMEM slot -> LDS.64
// (conflict-free). Staging regs transient -> 8 CTAs/SM, single wave.
// Interleaved permutation: tile0n covers real cols {2g}, tile1n {2g+1};
// lane (g,c) -> real cols 4c..4c+3 -> one plain float4 store per row.
// PASS 0: per-warp expsum partials.  PASS 1: lse from partials + write out.
template <int PASS>
__global__ __launch_bounds__(128, 8)
void k_proj(const float* __restrict__ wo, float* __restrict__ out) {
    __shared__ float2 s_b[4][3][4][32];    // [warp][stage][load][lane], 12 KB
    __shared__ float s_nl[32];
    int tid = threadIdx.x, lane = tid & 31, w = tid >> 5;
    int g = lane >> 2, c = lane & 3;
    int row0 = blockIdx.x * 32;
    int vbase = blockIdx.y * VQ + w * WCOLS;

    if (PASS == 1) {
        if (tid < 32) {
            float s = 0.f;
            #pragma unroll
            for (int q = 0; q < NPART; q++) s += g_part[(size_t)q * ROWS + row0 + tid];
            s_nl[tid] = -logf(s);
        }
        __syncthreads();
    }

    // ---- A fragments for the two m16 tiles ----
    uint32_t A0[4], A1[4];
    #pragma unroll
    for (int mt = 0; mt < 2; mt++) {
        int rb = row0 + mt * 16;
        const float* h0 = g_h + (size_t)(rb + g) * H_;
        const float* h8 = g_h + (size_t)(rb + g + 8) * H_;
        float2 x0 = *reinterpret_cast<const float2*>(h0 + 2 * c);
        float2 x1 = *reinterpret_cast<const float2*>(h8 + 2 * c);
        float2 x2 = *reinterpret_cast<const float2*>(h0 + 2 * c + 8);
        float2 x3 = *reinterpret_cast<const float2*>(h8 + 2 * c + 8);
        uint32_t* A = mt ? A1 : A0;
        A[0] = bf16x2_of(x0.x, x0.y);
        A[1] = bf16x2_of(x1.x, x1.y);
        A[2] = bf16x2_of(x2.x, x2.y);
        A[3] = bf16x2_of(x3.x, x3.y);
    }

    float nl00 = 0.f, nl01 = 0.f, nl10 = 0.f, nl11 = 0.f;
    if (PASS == 1) {
        nl00 = s_nl[g];      nl01 = s_nl[g + 8];
        nl10 = s_nl[16 + g]; nl11 = s_nl[16 + g + 8];
    }

    // B row pointers as float2: k = 2c, 2c+1, 2c+8, 2c+9 ; lane pair at col 2g
    const float2* q0 = reinterpret_cast<const float2*>(wo + (size_t)(2 * c) * V_ + vbase) + g;
    const float2* q1 = reinterpret_cast<const float2*>(wo + (size_t)(2 * c + 1) * V_ + vbase) + g;
    const float2* q2 = reinterpret_cast<const float2*>(wo + (size_t)(2 * c + 8) * V_ + vbase) + g;
    const float2* q3 = reinterpret_cast<const float2*>(wo + (size_t)(2 * c + 9) * V_ + vbase) + g;

    // per-lane staging base address
    uint32_t sl = (uint32_t)__cvta_generic_to_shared(&s_b[w][0][0][lane]);

    // prologue: stages for grp 0, 1
    #pragma unroll
    for (int p = 0; p < 2; p++) {
        int o = p * 8;                       // float2 units per 16 cols
        uint32_t sp = sl + (uint32_t)p * 1024u;
        cp8(sp + 0,   q0 + o);
        cp8(sp + 256, q1 + o);
        cp8(sp + 512, q2 + o);
        cp8(sp + 768, q3 + o);
        cp_commit();
    }

    float s0 = 0.f, s1 = 0.f, s2 = 0.f, s3 = 0.f;

    #pragma unroll 3
    for (int grp = 0; grp < NGRP; grp++) {
        cp_wait1();                          // stage grp ready
        int st = grp % 3;
        float2 f0 = s_b[w][st][0][lane];
        float2 f1 = s_b[w][st][1][lane];
        float2 f2 = s_b[w][st][2][lane];
        float2 f3 = s_b[w][st][3][lane];

        int ld = grp + 2;                    // refill stage (grp+2)%3
        if (ld < NGRP) {
            int sn = ld % 3;
            int o = ld * 8;
            uint32_t sp = sl + (uint32_t)sn * 1024u;
            cp8(sp + 0,   q0 + o);
            cp8(sp + 256, q1 + o);
            cp8(sp + 512, q2 + o);
            cp8(sp + 768, q3 + o);
        }
        cp_commit();                         // commit every iter (may be empty)

        // tile0n uses .x (even real cols 2g), tile1n uses .y (odd real cols)
        uint32_t b00 = bf16x2_of(f0.x, f1.x);
        uint32_t b01 = bf16x2_of(f2.x, f3.x);
        uint32_t b10 = bf16x2_of(f0.y, f1.y);
        uint32_t b11 = bf16x2_of(f2.y, f3.y);

        int col = vbase + grp * 16 + 4 * c;

        // ---- m-tile 0 ----
        {
            float c0 = 0.f, c1 = 0.f, c2 = 0.f, c3 = 0.f;
            float d0 = 0.f, d1 = 0.f, d2 = 0.f, d3 = 0.f;
            mma_bf16(c0, c1, c2, c3, A0, b00, b01);
            mma_bf16(d0, d1, d2, d3, A0, b10, b11);
            if (PASS == 0) {
                s0 += __expf(c0) + __expf(c1) + __expf(d0) + __expf(d1);
                s1 += __expf(c2) + __expf(c3) + __expf(d2) + __expf(d3);
            } else {
                float4 v0 = make_float4(c0 + nl00, d0 + nl00, c1 + nl00, d1 + nl00);
                float4 v1 = make_float4(c2 + nl01, d2 + nl01, c3 + nl01, d3 + nl01);
                *reinterpret_cast<float4*>(out + (size_t)(row0 + g) * V_ + col) = v0;
                *reinterpret_cast<float4*>(out + (size_t)(row0 + g + 8) * V_ + col) = v1;
            }
        }
        // ---- m-tile 1 ----
        {
            float c0 = 0.f, c1 = 0.f, c2 = 0.f, c3 = 0.f;
            float d0 = 0.f, d1 = 0.f, d2 = 0.f, d3 = 0.f;
            mma_bf16(c0, c1, c2, c3, A1, b00, b01);
            mma_bf16(d0, d1, d2, d3, A1, b10, b11);
            if (PASS == 0) {
                s2 += __expf(c0) + __expf(c1) + __expf(d0) + __expf(d1);
                s3 += __expf(c2) + __expf(c3) + __expf(d2) + __expf(d3);
            } else {
                float4 v0 = make_float4(c0 + nl10, d0 + nl10, c1 + nl10, d1 + nl10);
                float4 v1 = make_float4(c2 + nl11, d2 + nl11, c3 + nl11, d3 + nl11);
                *reinterpret_cast<float4*>(out + (size_t)(row0 + 16 + g) * V_ + col) = v0;
                *reinterpret_cast<float4*>(out + (size_t)(row0 + 24 + g) * V_ + col) = v1;
            }
        }
    }

    if (PASS == 0) {
        #pragma unroll
        for (int off = 1; off <= 2; off <<= 1) {
            s0 += __shfl_xor_sync(0xffffffffu, s0, off);
            s1 += __shfl_xor_sync(0xffffffffu, s1, off);
            s2 += __shfl_xor_sync(0xffffffffu, s2, off);
            s3 += __shfl_xor_sync(0xffffffffu, s3, off);
        }
        if (c == 0) {
            float* gp = g_part + (size_t)(blockIdx.y * 4 + w) * ROWS;
            gp[row0 + g]          = s0;
            gp[row0 + g + 8]      = s1;
            gp[row0 + 16 + g]     = s2;
            gp[row0 + 24 + g]     = s3;
        }
    }
}

// ---------------- launch --------------------------------------------------
extern "C" void kernel_launch(void* const* d_in, const int* in_sizes, int n_in,
                              void* d_out, int out_size) {
    const int*   idx    = (const int*)  d_in[0];
    const float* lookup = (const float*)d_in[1];
    const float* wx     = (const float*)d_in[2];
    const float* wh     = (const float*)d_in[3];
    const float* wo     = (const float*)d_in[4];
    const float* h0     = (const float*)d_in[5];
    float* out = (float*)d_out;

    k_embed_xw<<<ROWS / 128, 128>>>(idx, lookup, wx);
    k_rnn<<<1, B_ * H_>>>(wh, h0);
    k_proj<0><<<dim3(ROWS / 32, 4), 128>>>(wo, nullptr);
    k_proj<1><<<dim3(ROWS / 32, 4), 128>>>(wo, out);
}

// round 16
// speedup vs baseline: 1.1185x; 1.1185x over previous
#include <cuda_runtime.h>
#include <cuda_bf16.h>
#include <cstdint>
#include <cstddef>

#define S_    128
#define B_    64
#define V_    32000
#define E_    32
#define H_    16
#define ROWS  8192
#define VQ    8000              // cols per v-quarter
#define WCOLS 2000              // cols per warp
#define NGRP  (WCOLS / 16)      // 125 iterations, 16 cols each
#define NPART 16                // 4 v-quarters x 4 warps
#define LOG2E 1.4426950408889634f

// ---------------- device scratch ----------------
__device__ float g_xw[ROWS * H_];
__device__ float g_h[ROWS * H_];
__device__ float g_part[NPART * ROWS];

// ---------------- helpers ----------------
__device__ __forceinline__ uint32_t bf16x2_of(float lo, float hi) {
    uint32_t r;
    asm("cvt.rn.bf16x2.f32 %0, %1, %2;" : "=r"(r) : "f"(hi), "f"(lo));
    return r;
}
__device__ __forceinline__ float ex2f(float x) {
    float r;
    asm("ex2.approx.f32 %0, %1;" : "=f"(r) : "f"(x));
    return r;
}
__device__ __forceinline__ void mma_bf16(float& c0, float& c1, float& c2, float& c3,
                                         const uint32_t a[4], uint32_t b0, uint32_t b1) {
    asm volatile(
        "mma.sync.aligned.m16n8k16.row.col.f32.bf16.bf16.f32 "
        "{%0,%1,%2,%3}, {%4,%5,%6,%7}, {%8,%9}, {%0,%1,%2,%3};"
        : "+f"(c0), "+f"(c1), "+f"(c2), "+f"(c3)
        : "r"(a[0]), "r"(a[1]), "r"(a[2]), "r"(a[3]), "r"(b0), "r"(b1));
}

// ---------------- k1: xw = lookup[idx] @ Wx ----------------
__global__ void k_embed_xw(const int* __restrict__ idx,
                           const float* __restrict__ lookup,
                           const float* __restrict__ wx) {
    __shared__ float sWx[E_ * H_];
    for (int i = threadIdx.x; i < E_ * H_; i += blockDim.x) sWx[i] = wx[i];
    __syncthreads();
    int r = blockIdx.x * blockDim.x + threadIdx.x;
    int id = idx[r];
    float x[E_];
    const float4* lp = reinterpret_cast<const float4*>(lookup + (size_t)id * E_);
    #pragma unroll
    for (int i = 0; i < E_ / 4; i++) {
        float4 t = lp[i];
        x[4*i] = t.x; x[4*i+1] = t.y; x[4*i+2] = t.z; x[4*i+3] = t.w;
    }
    #pragma unroll
    for (int h = 0; h < H_; h++) {
        float a = 0.f;
        #pragma unroll
        for (int e = 0; e < E_; e++) a += x[e] * sWx[e * H_ + h];
        g_xw[r * H_ + h] = a;
    }
}

// ---------------- k2: sequential recurrence (ping-pong) ----------------
__global__ void k_rnn(const float* __restrict__ wh, const float* __restrict__ h0) {
    __shared__ float sWh[H_ * H_];
    __shared__ float sh[2][B_ * H_];
    int tid = threadIdx.x;                 // 1024 threads
    if (tid < H_ * H_) sWh[tid] = wh[tid];
    sh[0][tid] = h0[tid];
    __syncthreads();
    int b = tid >> 4, j = tid & 15;
    float pre = g_xw[tid];
    #pragma unroll 2
    for (int s = 0; s < S_; s++) {
        int p = s & 1;
        float a = pre;
        float nxt = (s < S_ - 1) ? g_xw[(s + 1) * (B_ * H_) + tid] : 0.f;
        #pragma unroll
        for (int k = 0; k < H_; k++) a += sh[p][b * H_ + k] * sWh[k * H_ + j];
        float hn = tanhf(a);
        sh[p ^ 1][tid] = hn;
        g_h[s * (B_ * H_) + tid] = hn;
        pre = nxt;
        __syncthreads();
    }
}

// ========================================================================
// Shared projection geometry (R14-proven):
//  CTA: 128 thr / 4 warps / 32 rows (2 m-tiles per warp), grid (256, 4).
//  Warp owns 2000 cols; 16 cols/iter via two interleaved n8 tiles:
//  tile0n real cols {2g}, tile1n {2g+1}; lane (g,c) loads per k-row the
//  adjacent pair (2g,2g+1) as one float2 (4x coalesced LDG.64/iter);
//  accumulators land on real cols 4c..4c+3.
// ========================================================================

// ---------------- pass 0: expsum partials (log2-domain, 8 CTAs/SM) ------
__global__ __launch_bounds__(128, 8)
void k_proj0(const float* __restrict__ wo) {
    int tid = threadIdx.x, lane = tid & 31, w = tid >> 5;
    int g = lane >> 2, c = lane & 3;
    int row0 = blockIdx.x * 32;
    int vbase = blockIdx.y * VQ + w * WCOLS;

    // A fragments scaled by log2(e): logits come out in base-2 domain.
    uint32_t A0[4], A1[4];
    #pragma unroll
    for (int mt = 0; mt < 2; mt++) {
        int rb = row0 + mt * 16;
        const float* h0 = g_h + (size_t)(rb + g) * H_;
        const float* h8 = g_h + (size_t)(rb + g + 8) * H_;
        float2 x0 = *reinterpret_cast<const float2*>(h0 + 2 * c);
        float2 x1 = *reinterpret_cast<const float2*>(h8 + 2 * c);
        float2 x2 = *reinterpret_cast<const float2*>(h0 + 2 * c + 8);
        float2 x3 = *reinterpret_cast<const float2*>(h8 + 2 * c + 8);
        uint32_t* A = mt ? A1 : A0;
        A[0] = bf16x2_of(x0.x * LOG2E, x0.y * LOG2E);
        A[1] = bf16x2_of(x1.x * LOG2E, x1.y * LOG2E);
        A[2] = bf16x2_of(x2.x * LOG2E, x2.y * LOG2E);
        A[3] = bf16x2_of(x3.x * LOG2E, x3.y * LOG2E);
    }

    const float2* q0 = reinterpret_cast<const float2*>(wo + (size_t)(2 * c) * V_ + vbase) + g;
    const float2* q1 = reinterpret_cast<const float2*>(wo + (size_t)(2 * c + 1) * V_ + vbase) + g;
    const float2* q2 = reinterpret_cast<const float2*>(wo + (size_t)(2 * c + 8) * V_ + vbase) + g;
    const float2* q3 = reinterpret_cast<const float2*>(wo + (size_t)(2 * c + 9) * V_ + vbase) + g;

    float s0 = 0.f, s1 = 0.f, s2 = 0.f, s3 = 0.f;

    float2 f[2][4];
    f[0][0] = __ldg(q0); f[0][1] = __ldg(q1);
    f[0][2] = __ldg(q2); f[0][3] = __ldg(q3);

    #pragma unroll 2
    for (int grp = 0; grp < NGRP; grp++) {
        int st = grp & 1, ns = st ^ 1;
        int no = (grp + 1 < NGRP ? grp + 1 : grp) * 8;
        f[ns][0] = __ldg(q0 + no); f[ns][1] = __ldg(q1 + no);
        f[ns][2] = __ldg(q2 + no); f[ns][3] = __ldg(q3 + no);

        uint32_t b00 = bf16x2_of(f[st][0].x, f[st][1].x);
        uint32_t b01 = bf16x2_of(f[st][2].x, f[st][3].x);
        uint32_t b10 = bf16x2_of(f[st][0].y, f[st][1].y);
        uint32_t b11 = bf16x2_of(f[st][2].y, f[st][3].y);

        float c0 = 0.f, c1 = 0.f, c2 = 0.f, c3 = 0.f;
        float d0 = 0.f, d1 = 0.f, d2 = 0.f, d3 = 0.f;
        mma_bf16(c0, c1, c2, c3, A0, b00, b01);
        mma_bf16(d0, d1, d2, d3, A0, b10, b11);
        float e0 = 0.f, e1 = 0.f, e2 = 0.f, e3 = 0.f;
        float h0_ = 0.f, h1_ = 0.f, h2_ = 0.f, h3_ = 0.f;
        mma_bf16(e0, e1, e2, e3, A1, b00, b01);
        mma_bf16(h0_, h1_, h2_, h3_, A1, b10, b11);

        // interleave EX2 chains across accumulators (MUFU pipelining)
        s0 += ex2f(c0) + ex2f(c1) + ex2f(d0) + ex2f(d1);
        s1 += ex2f(c2) + ex2f(c3) + ex2f(d2) + ex2f(d3);
        s2 += ex2f(e0) + ex2f(e1) + ex2f(h0_) + ex2f(h1_);
        s3 += ex2f(e2) + ex2f(e3) + ex2f(h2_) + ex2f(h3_);
    }

    #pragma unroll
    for (int off = 1; off <= 2; off <<= 1) {
        s0 += __shfl_xor_sync(0xffffffffu, s0, off);
        s1 += __shfl_xor_sync(0xffffffffu, s1, off);
        s2 += __shfl_xor_sync(0xffffffffu, s2, off);
        s3 += __shfl_xor_sync(0xffffffffu, s3, off);
    }
    if (c == 0) {
        float* gp = g_part + (size_t)(blockIdx.y * 4 + w) * ROWS;
        gp[row0 + g]          = s0;
        gp[row0 + g + 8]      = s1;
        gp[row0 + 16 + g]     = s2;
        gp[row0 + 24 + g]     = s3;
    }
}

// ---------------- pass 1: lse from partials + write out (R14-identical) --
__global__ __launch_bounds__(128, 7)
void k_proj1(const float* __restrict__ wo, float* __restrict__ out) {
    __shared__ float s_nl[32];
    int tid = threadIdx.x, lane = tid & 31, w = tid >> 5;
    int g = lane >> 2, c = lane & 3;
    int row0 = blockIdx.x * 32;
    int vbase = blockIdx.y * VQ + w * WCOLS;

    if (tid < 32) {
        float s = 0.f;
        #pragma unroll
        for (int q = 0; q < NPART; q++) s += g_part[(size_t)q * ROWS + row0 + tid];
        s_nl[tid] = -logf(s);
    }
    __syncthreads();

    uint32_t A0[4], A1[4];
    #pragma unroll
    for (int mt = 0; mt < 2; mt++) {
        int rb = row0 + mt * 16;
        const float* h0 = g_h + (size_t)(rb + g) * H_;
        const float* h8 = g_h + (size_t)(rb + g + 8) * H_;
        float2 x0 = *reinterpret_cast<const float2*>(h0 + 2 * c);
        float2 x1 = *reinterpret_cast<const float2*>(h8 + 2 * c);
        float2 x2 = *reinterpret_cast<const float2*>(h0 + 2 * c + 8);
        float2 x3 = *reinterpret_cast<const float2*>(h8 + 2 * c + 8);
        uint32_t* A = mt ? A1 : A0;
        A[0] = bf16x2_of(x0.x, x0.y);
        A[1] = bf16x2_of(x1.x, x1.y);
        A[2] = bf16x2_of(x2.x, x2.y);
        A[3] = bf16x2_of(x3.x, x3.y);
    }

    float nl00 = s_nl[g],      nl01 = s_nl[g + 8];
    float nl10 = s_nl[16 + g], nl11 = s_nl[16 + g + 8];

    const float2* q0 = reinterpret_cast<const float2*>(wo + (size_t)(2 * c) * V_ + vbase) + g;
    const float2* q1 = reinterpret_cast<const float2*>(wo + (size_t)(2 * c + 1) * V_ + vbase) + g;
    const float2* q2 = reinterpret_cast<const float2*>(wo + (size_t)(2 * c + 8) * V_ + vbase) + g;
    const float2* q3 = reinterpret_cast<const float2*>(wo + (size_t)(2 * c + 9) * V_ + vbase) + g;

    float2 f[2][4];
    f[0][0] = __ldg(q0); f[0][1] = __ldg(q1);
    f[0][2] = __ldg(q2); f[0][3] = __ldg(q3);

    #pragma unroll 2
    for (int grp = 0; grp < NGRP; grp++) {
        int st = grp & 1, ns = st ^ 1;
        int no = (grp + 1 < NGRP ? grp + 1 : grp) * 8;
        f[ns][0] = __ldg(q0 + no); f[ns][1] = __ldg(q1 + no);
        f[ns][2] = __ldg(q2 + no); f[ns][3] = __ldg(q3 + no);

        uint32_t b00 = bf16x2_of(f[st][0].x, f[st][1].x);
        uint32_t b01 = bf16x2_of(f[st][2].x, f[st][3].x);
        uint32_t b10 = bf16x2_of(f[st][0].y, f[st][1].y);
        uint32_t b11 = bf16x2_of(f[st][2].y, f[st][3].y);

        int col = vbase + grp * 16 + 4 * c;

        {
            float c0 = 0.f, c1 = 0.f, c2 = 0.f, c3 = 0.f;
            float d0 = 0.f, d1 = 0.f, d2 = 0.f, d3 = 0.f;
            mma_bf16(c0, c1, c2, c3, A0, b00, b01);
            mma_bf16(d0, d1, d2, d3, A0, b10, b11);
            float4 v0 = make_float4(c0 + nl00, d0 + nl00, c1 + nl00, d1 + nl00);
            float4 v1 = make_float4(c2 + nl01, d2 + nl01, c3 + nl01, d3 + nl01);
            *reinterpret_cast<float4*>(out + (size_t)(row0 + g) * V_ + col) = v0;
            *reinterpret_cast<float4*>(out + (size_t)(row0 + g + 8) * V_ + col) = v1;
        }
        {
            float c0 = 0.f, c1 = 0.f, c2 = 0.f, c3 = 0.f;
            float d0 = 0.f, d1 = 0.f, d2 = 0.f, d3 = 0.f;
            mma_bf16(c0, c1, c2, c3, A1, b00, b01);
            mma_bf16(d0, d1, d2, d3, A1, b10, b11);
            float4 v0 = make_float4(c0 + nl10, d0 + nl10, c1 + nl10, d1 + nl10);
            float4 v1 = make_float4(c2 + nl11, d2 + nl11, c3 + nl11, d3 + nl11);
            *reinterpret_cast<float4*>(out + (size_t)(row0 + 16 + g) * V_ + col) = v0;
            *reinterpret_cast<float4*>(out + (size_t)(row0 + 24 + g) * V_ + col) = v1;
        }
    }
}

// ---------------- launch --------------------------------------------------
extern "C" void kernel_launch(void* const* d_in, const int* in_sizes, int n_in,
                              void* d_out, int out_size) {
    const int*   idx    = (const int*)  d_in[0];
    const float* lookup = (const float*)d_in[1];
    const float* wx     = (const float*)d_in[2];
    const float* wh     = (const float*)d_in[3];
    const float* wo     = (const float*)d_in[4];
    const float* h0     = (const float*)d_in[5];
    float* out = (float*)d_out;

    k_embed_xw<<<ROWS / 128, 128>>>(idx, lookup, wx);
    k_rnn<<<1, B_ * H_>>>(wh, h0);
    k_proj0<<<dim3(ROWS / 32, 4), 128>>>(wo);
    k_proj1<<<dim3(ROWS / 32, 4), 128>>>(wo, out);
}